// round 1
// baseline (speedup 1.0000x reference)
#include <cuda_runtime.h>
#include <cstdint>

#define BATCH  4
#define SEQ    4096
#define HID    4096
#define OUTF   4096
#define RANK   64
#define NADAPT 8
#define KSPLIT 4

typedef unsigned long long ull;

// Split-K partials of stage 1, stored rank-major: [kp][b][r][s]
__device__ float g_bxp[(size_t)KSPLIT * BATCH * RANK * SEQ];

__device__ __forceinline__ ull pack2(float lo, float hi) {
    ull r; asm("mov.b64 %0, {%1,%2};" : "=l"(r) : "f"(lo), "f"(hi)); return r;
}
__device__ __forceinline__ void unpack2(ull v, float &lo, float &hi) {
    asm("mov.b64 {%0,%1}, %2;" : "=f"(lo), "=f"(hi) : "l"(v));
}
__device__ __forceinline__ void ffma2(ull &d, ull a, ull b) {
    asm("fma.rn.f32x2 %0, %1, %2, %0;" : "+l"(d) : "l"(a), "l"(b));
}

// ============================================================================
// Stage 1 (sdd): Bx_part[kp][b][r][s] = sum_{h in k-split} x[b][s][h] * B[h][a][r]
// Tile: M(seq)=128 x N(rank)=64, K chunk = 32, split-K = 4. 256 threads.
// Micro-tile per thread: 8M x 4N, accumulated as f32x2 pairs along M.
// ============================================================================
__global__ __launch_bounds__(256) void lora_sdd(
    const float* __restrict__ x, const int* __restrict__ ids,
    const float* __restrict__ Bw)
{
    __shared__ float Xs[32][132];   // [k][m], padded; row start 528B (16B aligned)
    __shared__ float Bs[32][64];    // [k][r]

    const int mt = blockIdx.x;      // 0..31  seq tile
    const int b  = blockIdx.y;      // 0..3   batch
    const int kp = blockIdx.z;      // 0..3   k split
    const int a  = ids[b];
    const int m0 = mt * 128;
    const int k0 = kp * (HID / KSPLIT);

    const int tid = threadIdx.x;
    const int tx  = tid & 15;       // rank group: r = tx*4 + n
    const int ty  = tid >> 4;       // seq group:  s = m0 + ty*8 + ...

    ull acc[4][4];
    #pragma unroll
    for (int i = 0; i < 4; ++i)
        #pragma unroll
        for (int j = 0; j < 4; ++j) acc[i][j] = 0ull;

    for (int kc = 0; kc < HID / KSPLIT; kc += 32) {
        // ---- load X tile (128 x 32) transposed into Xs[k][m] ----
        #pragma unroll
        for (int it = 0; it < 4; ++it) {
            int idx = tid + it * 256;        // 0..1023 float4 slots
            int m  = idx >> 3;               // 0..127
            int kg = idx & 7;                // 0..7 (4 k each)
            const float4 v = *(const float4*)(
                x + (size_t)(b * SEQ + m0 + m) * HID + (k0 + kc) + kg * 4);
            Xs[kg * 4 + 0][m] = v.x;
            Xs[kg * 4 + 1][m] = v.y;
            Xs[kg * 4 + 2][m] = v.z;
            Xs[kg * 4 + 3][m] = v.w;
        }
        // ---- load B tile (32 x 64) into Bs[k][r] ----
        #pragma unroll
        for (int it = 0; it < 2; ++it) {
            int idx = tid + it * 256;        // 0..511 float4 slots
            int h  = idx >> 4;               // 0..31
            int rg = idx & 15;               // 0..15
            *(float4*)&Bs[h][rg * 4] = *(const float4*)(
                Bw + (size_t)(k0 + kc + h) * (NADAPT * RANK) + a * RANK + rg * 4);
        }
        __syncthreads();

        #pragma unroll
        for (int k = 0; k < 32; ++k) {
            // 8 consecutive M values as four f32x2 pairs (direct 128-bit loads)
            ulonglong2 x01 = *(ulonglong2*)&Xs[k][ty * 8];
            ulonglong2 x23 = *(ulonglong2*)&Xs[k][ty * 8 + 4];
            float4 bv = *(float4*)&Bs[k][tx * 4];
            ull b0 = pack2(bv.x, bv.x);
            ull b1 = pack2(bv.y, bv.y);
            ull b2 = pack2(bv.z, bv.z);
            ull b3 = pack2(bv.w, bv.w);
            ffma2(acc[0][0], x01.x, b0); ffma2(acc[0][1], x01.x, b1);
            ffma2(acc[0][2], x01.x, b2); ffma2(acc[0][3], x01.x, b3);
            ffma2(acc[1][0], x01.y, b0); ffma2(acc[1][1], x01.y, b1);
            ffma2(acc[1][2], x01.y, b2); ffma2(acc[1][3], x01.y, b3);
            ffma2(acc[2][0], x23.x, b0); ffma2(acc[2][1], x23.x, b1);
            ffma2(acc[2][2], x23.x, b2); ffma2(acc[2][3], x23.x, b3);
            ffma2(acc[3][0], x23.y, b0); ffma2(acc[3][1], x23.y, b1);
            ffma2(acc[3][2], x23.y, b2); ffma2(acc[3][3], x23.y, b3);
        }
        __syncthreads();
    }

    // ---- epilogue: each acc[mp][n] is an (s, s+1) pair -> one 8B store ----
    #pragma unroll
    for (int mp = 0; mp < 4; ++mp) {
        int s = m0 + ty * 8 + mp * 2;
        #pragma unroll
        for (int n = 0; n < 4; ++n) {
            int r = tx * 4 + n;
            *(ull*)(g_bxp + (size_t)((kp * BATCH + b) * RANK + r) * SEQ + s)
                = acc[mp][n];
        }
    }
}

// ============================================================================
// Stage 2 (dsd): out[b][s][o] = (1/64) * sum_r Bx[b][s][r] * A[a][r][o]
// Tile: M(seq)=64 x N(out)=128, K = RANK = 64 (single pass). 256 threads.
// Sums the 4 split-K partials while loading Bxs. Micro-tile 8M x 4N (f32x2).
// ============================================================================
__global__ __launch_bounds__(256) void lora_dsd(
    const int* __restrict__ ids, const float* __restrict__ A,
    float* __restrict__ out)
{
    __shared__ float Bxs[64][64];    // [r][s]  (16 KB)
    __shared__ float As [64][128];   // [r][o]  (32 KB)

    const int nt = blockIdx.x;       // 0..31  out tile
    const int mt = blockIdx.y;       // 0..63  seq tile
    const int b  = blockIdx.z;       // 0..3
    const int a  = ids[b];
    const int m0 = mt * 64;
    const int o0 = nt * 128;

    const int tid = threadIdx.x;
    const int tx  = tid & 31;        // out group: o = o0 + tx*4 + n
    const int ty  = tid >> 5;        // seq group: s = m0 + ty*8 + ...

    // ---- load Bx tile (64r x 64s), summing the 4 split-K partials ----
    #pragma unroll
    for (int it = 0; it < 4; ++it) {
        int idx = tid + it * 256;    // 0..1023 float4 slots
        int r  = idx >> 4;           // 0..63
        int sg = idx & 15;           // 0..15
        size_t base = (size_t)(b * RANK + r) * SEQ + m0 + sg * 4;
        const size_t stride = (size_t)BATCH * RANK * SEQ;
        float4 v0 = *(const float4*)(g_bxp + base + 0 * stride);
        float4 v1 = *(const float4*)(g_bxp + base + 1 * stride);
        float4 v2 = *(const float4*)(g_bxp + base + 2 * stride);
        float4 v3 = *(const float4*)(g_bxp + base + 3 * stride);
        float4 s;
        s.x = (v0.x + v1.x) + (v2.x + v3.x);
        s.y = (v0.y + v1.y) + (v2.y + v3.y);
        s.z = (v0.z + v1.z) + (v2.z + v3.z);
        s.w = (v0.w + v1.w) + (v2.w + v3.w);
        *(float4*)&Bxs[r][sg * 4] = s;
    }
    // ---- load A tile (64r x 128o) ----
    #pragma unroll
    for (int it = 0; it < 8; ++it) {
        int idx = tid + it * 256;    // 0..2047 float4 slots
        int r  = idx >> 5;           // 0..63
        int og = idx & 31;           // 0..31
        *(float4*)&As[r][og * 4] = *(const float4*)(
            A + (size_t)a * RANK * OUTF + (size_t)r * OUTF + o0 + og * 4);
    }
    __syncthreads();

    ull acc[4][4];
    #pragma unroll
    for (int i = 0; i < 4; ++i)
        #pragma unroll
        for (int j = 0; j < 4; ++j) acc[i][j] = 0ull;

    #pragma unroll 16
    for (int k = 0; k < RANK; ++k) {
        ulonglong2 x01 = *(ulonglong2*)&Bxs[k][ty * 8];
        ulonglong2 x23 = *(ulonglong2*)&Bxs[k][ty * 8 + 4];
        float4 av = *(float4*)&As[k][tx * 4];
        ull a0 = pack2(av.x, av.x);
        ull a1 = pack2(av.y, av.y);
        ull a2 = pack2(av.z, av.z);
        ull a3 = pack2(av.w, av.w);
        ffma2(acc[0][0], x01.x, a0); ffma2(acc[0][1], x01.x, a1);
        ffma2(acc[0][2], x01.x, a2); ffma2(acc[0][3], x01.x, a3);
        ffma2(acc[1][0], x01.y, a0); ffma2(acc[1][1], x01.y, a1);
        ffma2(acc[1][2], x01.y, a2); ffma2(acc[1][3], x01.y, a3);
        ffma2(acc[2][0], x23.x, a0); ffma2(acc[2][1], x23.x, a1);
        ffma2(acc[2][2], x23.x, a2); ffma2(acc[2][3], x23.x, a3);
        ffma2(acc[3][0], x23.y, a0); ffma2(acc[3][1], x23.y, a1);
        ffma2(acc[3][2], x23.y, a2); ffma2(acc[3][3], x23.y, a3);
    }

    const float scale = 1.0f / (float)RANK;   // ALPHA / RANK
    #pragma unroll
    for (int mp = 0; mp < 4; ++mp) {
        float lo[4], hi[4];
        #pragma unroll
        for (int n = 0; n < 4; ++n) unpack2(acc[mp][n], lo[n], hi[n]);
        int s = m0 + ty * 8 + mp * 2;
        float4 v0 = { lo[0] * scale, lo[1] * scale, lo[2] * scale, lo[3] * scale };
        float4 v1 = { hi[0] * scale, hi[1] * scale, hi[2] * scale, hi[3] * scale };
        *(float4*)(out + (size_t)(b * SEQ + s)     * OUTF + o0 + tx * 4) = v0;
        *(float4*)(out + (size_t)(b * SEQ + s + 1) * OUTF + o0 + tx * 4) = v1;
    }
}

extern "C" void kernel_launch(void* const* d_in, const int* in_sizes, int n_in,
                              void* d_out, int out_size)
{
    const float* x   = (const float*)d_in[0];
    const int*   ids = (const int*)  d_in[1];
    const float* A   = (const float*)d_in[2];
    const float* Bw  = (const float*)d_in[3];
    float* out = (float*)d_out;

    lora_sdd<<<dim3(SEQ / 128, BATCH, KSPLIT), 256>>>(x, ids, Bw);
    lora_dsd<<<dim3(OUTF / 128, SEQ / 64, BATCH), 256>>>(ids, A, out);
}

// round 4
// speedup vs baseline: 1.4324x; 1.4324x over previous
#include <cuda_runtime.h>
#include <cuda_bf16.h>
#include <cstdint>

#define BATCH  4
#define SEQ    4096
#define HID    4096
#define OUTF   4096
#define RANK   64
#define NADAPT 8

// ---------------------------------------------------------------------------
// Global scratch (bf16 split pairs, packed 2 x bf16 per uint32)
// Bx: [b][s][r]   A-transposed: [a][o][r]
// ---------------------------------------------------------------------------
__device__ __align__(16) uint32_t g_bxh[BATCH * SEQ * RANK / 2];
__device__ __align__(16) uint32_t g_bxl[BATCH * SEQ * RANK / 2];
__device__ __align__(16) uint32_t g_ath[NADAPT * OUTF * RANK / 2];
__device__ __align__(16) uint32_t g_atl[NADAPT * OUTF * RANK / 2];

#define SW128(b) ((b) ^ (((b) >> 3) & 0x70))

__device__ __forceinline__ uint32_t smem_u32(const void* p) {
    uint32_t a;
    asm("{ .reg .u64 t; cvta.to.shared.u64 t, %1; cvt.u32.u64 %0, t; }"
        : "=r"(a) : "l"(p));
    return a;
}

__device__ __forceinline__ void ldsm4(uint32_t r[4], uint32_t addr) {
    asm volatile("ldmatrix.sync.aligned.m8n8.x4.shared.b16 {%0,%1,%2,%3}, [%4];"
        : "=r"(r[0]), "=r"(r[1]), "=r"(r[2]), "=r"(r[3]) : "r"(addr));
}

__device__ __forceinline__ void mma16816(float c[4], const uint32_t a[4],
                                         uint32_t b0, uint32_t b1) {
    asm volatile(
        "mma.sync.aligned.m16n8k16.row.col.f32.bf16.bf16.f32 "
        "{%0,%1,%2,%3}, {%4,%5,%6,%7}, {%8,%9}, {%0,%1,%2,%3};"
        : "+f"(c[0]), "+f"(c[1]), "+f"(c[2]), "+f"(c[3])
        : "r"(a[0]), "r"(a[1]), "r"(a[2]), "r"(a[3]), "r"(b0), "r"(b1));
}

// 3-term split-precision accumulate: c += Ah*Bh + Ah*Bl + Al*Bh
__device__ __forceinline__ void mma3(float c[4],
        const uint32_t ah[4], const uint32_t al[4],
        uint32_t bh0, uint32_t bh1, uint32_t bl0, uint32_t bl1) {
    mma16816(c, ah, bh0, bh1);
    mma16816(c, ah, bl0, bl1);
    mma16816(c, al, bh0, bh1);
}

// bf16 hi/lo split of a float pair -> two packed bf16x2 words (lo elem = a)
__device__ __forceinline__ void split2(float a, float b, uint32_t &h, uint32_t &l) {
    uint32_t hp;
    asm("cvt.rn.bf16x2.f32 %0, %1, %2;" : "=r"(hp) : "f"(b), "f"(a));
    float fa = __uint_as_float(hp << 16);
    float fb = __uint_as_float(hp & 0xFFFF0000u);
    float ra = a - fa, rb = b - fb;
    uint32_t lp;
    asm("cvt.rn.bf16x2.f32 %0, %1, %2;" : "=r"(lp) : "f"(rb), "f"(ra));
    h = hp; l = lp;
}
__device__ __forceinline__ void split1(float a, uint16_t &h, uint16_t &l) {
    uint16_t hb;
    asm("cvt.rn.bf16.f32 %0, %1;" : "=h"(hb) : "f"(a));
    float fa = __uint_as_float(((uint32_t)hb) << 16);
    float r = a - fa;
    uint16_t lb;
    asm("cvt.rn.bf16.f32 %0, %1;" : "=h"(lb) : "f"(r));
    h = hb; l = lb;
}

// ===========================================================================
// prep_A: A[a][r][o] fp32 -> g_ath/g_atl [a][o][r] bf16 (K-major)
// grid (32 o-tiles, 8 adapters), 256 thr
// ===========================================================================
__global__ __launch_bounds__(256) void lora_prep_a(const float* __restrict__ A) {
    __shared__ float As[64][132];
    const int a  = blockIdx.y;
    const int o0 = blockIdx.x * 128;
    const int tid = threadIdx.x;

    #pragma unroll
    for (int i = 0; i < 8; ++i) {
        int idx = tid + i * 256;          // 2048 float4 slots
        int r = idx >> 5, og = idx & 31;
        *(float4*)&As[r][og * 4] =
            *(const float4*)(A + (size_t)a * RANK * OUTF + (size_t)r * OUTF + o0 + og * 4);
    }
    __syncthreads();

    const int o = tid >> 1, r0 = (tid & 1) * 32;
    __align__(16) uint32_t hb[16], lb[16];
    #pragma unroll
    for (int j = 0; j < 16; ++j)
        split2(As[r0 + 2 * j][o], As[r0 + 2 * j + 1][o], hb[j], lb[j]);

    size_t base = ((size_t)(a * OUTF + o0 + o) * RANK + r0) / 2;   // uint32 units
    #pragma unroll
    for (int q = 0; q < 4; ++q) {
        *(uint4*)(g_ath + base + q * 4) = *(uint4*)(hb + q * 4);
        *(uint4*)(g_atl + base + q * 4) = *(uint4*)(lb + q * 4);
    }
}

// ===========================================================================
// Stage 1: Bx[b][s][r] = x[b][s][:] @ B[:][a][r]
// CTA 128M x 64N, K=4096 in 64-chunks. 8 warps = 4M x 2N, warp tile 32x32.
// Fused fp32->bf16 hi/lo conversion; ldmatrix + mma.sync bf16, 3-term split.
// ===========================================================================
__global__ __launch_bounds__(256) void lora_s1(
    const float* __restrict__ x, const int* __restrict__ ids,
    const float* __restrict__ Bw)
{
    __shared__ __align__(128) uint8_t sXh[128 * 128];   // [m][k] bf16, SW128
    __shared__ __align__(128) uint8_t sXl[128 * 128];
    __shared__ __align__(128) uint8_t sBh[64 * 128];    // [r][k] bf16, SW128
    __shared__ __align__(128) uint8_t sBl[64 * 128];

    const int tid = threadIdx.x, lane = tid & 31, wid = tid >> 5;
    const int wm = wid & 3, wn = wid >> 2;
    const int b = blockIdx.y;
    const int a = ids[b];
    const int m0 = blockIdx.x * 128;

    const uint32_t xh_b = smem_u32(sXh), xl_b = smem_u32(sXl);
    const uint32_t bh_b = smem_u32(sBh), bl_b = smem_u32(sBl);

    const int lr = lane & 15;
    const uint32_t lcol = (uint32_t)(lane >> 4) * 16;

    uint32_t aterm[2], axor[2], bterm[2], bxor[2];
    #pragma unroll
    for (int t = 0; t < 2; ++t) {
        int ar = wm * 32 + t * 16 + lr;
        aterm[t] = (uint32_t)ar * 128; axor[t] = (uint32_t)(ar & 7) << 4;
        int br = wn * 32 + t * 16 + lr;
        bterm[t] = (uint32_t)br * 128; bxor[t] = (uint32_t)(br & 7) << 4;
    }

    float acc[2][4][4];
    #pragma unroll
    for (int i = 0; i < 2; ++i)
        #pragma unroll
        for (int j = 0; j < 4; ++j)
            #pragma unroll
            for (int k = 0; k < 4; ++k) acc[i][j][k] = 0.f;

    float4 xv[8], bv[4];
    // prefetch chunk 0
    #pragma unroll
    for (int i = 0; i < 8; ++i) {
        int idx = tid + i * 256;
        int m = idx >> 4, kg = idx & 15;
        xv[i] = *(const float4*)(x + (size_t)(b * SEQ + m0 + m) * HID + kg * 4);
    }
    #pragma unroll
    for (int i = 0; i < 4; ++i) {
        int idx = tid + i * 256;
        int h = idx >> 4, rg = idx & 15;
        bv[i] = *(const float4*)(Bw + (size_t)h * (NADAPT * RANK) + a * RANK + rg * 4);
    }

    for (int it = 0; it < HID / 64; ++it) {
        // ---- convert current chunk into smem (hi/lo bf16, SW128) ----
        #pragma unroll
        for (int i = 0; i < 8; ++i) {
            int idx = tid + i * 256;
            int m = idx >> 4, kg = idx & 15;
            uint32_t h0, l0, h1, l1;
            split2(xv[i].x, xv[i].y, h0, l0);
            split2(xv[i].z, xv[i].w, h1, l1);
            uint32_t off = (uint32_t)m * 128 + kg * 8;
            uint32_t s0 = SW128(off), s1 = SW128(off + 4);
            *(uint32_t*)(sXh + s0) = h0;
            *(uint32_t*)(sXl + s0) = l0;
            *(uint32_t*)(sXh + s1) = h1;
            *(uint32_t*)(sXl + s1) = l1;
        }
        #pragma unroll
        for (int i = 0; i < 4; ++i) {
            int idx = tid + i * 256;
            int h = idx >> 4, rg = idx & 15;
            const float* f = &bv[i].x;
            #pragma unroll
            for (int j = 0; j < 4; ++j) {
                uint16_t hh, ll;
                split1(f[j], hh, ll);
                uint32_t so = SW128((uint32_t)(rg * 4 + j) * 128 + h * 2);
                *(uint16_t*)(sBh + so) = hh;
                *(uint16_t*)(sBl + so) = ll;
            }
        }
        __syncthreads();

        // ---- prefetch next chunk (LDG latency overlaps MMA below) ----
        if (it + 1 < HID / 64) {
            int kc = (it + 1) * 64;
            #pragma unroll
            for (int i = 0; i < 8; ++i) {
                int idx = tid + i * 256;
                int m = idx >> 4, kg = idx & 15;
                xv[i] = *(const float4*)(x + (size_t)(b * SEQ + m0 + m) * HID + kc + kg * 4);
            }
            #pragma unroll
            for (int i = 0; i < 4; ++i) {
                int idx = tid + i * 256;
                int h = idx >> 4, rg = idx & 15;
                bv[i] = *(const float4*)(Bw + (size_t)(kc + h) * (NADAPT * RANK) + a * RANK + rg * 4);
            }
        }

        // ---- 4 k-steps of m16n8k16 ----
        #pragma unroll
        for (int ks = 0; ks < 4; ++ks) {
            uint32_t cb = lcol + (uint32_t)ks * 32;
            uint32_t ah0[4], ah1[4], al0[4], al1[4];
            ldsm4(ah0, xh_b + aterm[0] + (cb ^ axor[0]));
            ldsm4(ah1, xh_b + aterm[1] + (cb ^ axor[1]));
            ldsm4(al0, xl_b + aterm[0] + (cb ^ axor[0]));
            ldsm4(al1, xl_b + aterm[1] + (cb ^ axor[1]));
            uint32_t bh0[4], bh1[4], bl0[4], bl1[4];
            ldsm4(bh0, bh_b + bterm[0] + (cb ^ bxor[0]));
            ldsm4(bh1, bh_b + bterm[1] + (cb ^ bxor[1]));
            ldsm4(bl0, bl_b + bterm[0] + (cb ^ bxor[0]));
            ldsm4(bl1, bl_b + bterm[1] + (cb ^ bxor[1]));

            mma3(acc[0][0], ah0, al0, bh0[0], bh0[2], bl0[0], bl0[2]);
            mma3(acc[0][1], ah0, al0, bh0[1], bh0[3], bl0[1], bl0[3]);
            mma3(acc[0][2], ah0, al0, bh1[0], bh1[2], bl1[0], bl1[2]);
            mma3(acc[0][3], ah0, al0, bh1[1], bh1[3], bl1[1], bl1[3]);
            mma3(acc[1][0], ah1, al1, bh0[0], bh0[2], bl0[0], bl0[2]);
            mma3(acc[1][1], ah1, al1, bh0[1], bh0[3], bl0[1], bl0[3]);
            mma3(acc[1][2], ah1, al1, bh1[0], bh1[2], bl1[0], bl1[2]);
            mma3(acc[1][3], ah1, al1, bh1[1], bh1[3], bl1[1], bl1[3]);
        }
        __syncthreads();
    }

    // ---- epilogue: c-pairs are adjacent r values -> bf16 hi/lo packed ----
    #pragma unroll
    for (int mt = 0; mt < 2; ++mt)
        #pragma unroll
        for (int nt = 0; nt < 4; ++nt)
            #pragma unroll
            for (int rh = 0; rh < 2; ++rh) {
                int s = m0 + wm * 32 + mt * 16 + rh * 8 + (lane >> 2);
                int r = wn * 32 + nt * 8 + 2 * (lane & 3);
                uint32_t h, l;
                split2(acc[mt][nt][2 * rh], acc[mt][nt][2 * rh + 1], h, l);
                size_t idx = (size_t)(b * SEQ + s) * (RANK / 2) + (r >> 1);
                g_bxh[idx] = h;
                g_bxl[idx] = l;
            }
}

// ===========================================================================
// Stage 2: out[b][s][o] = Bx[b][s][:] @ At[a][o][:] / 64
// CTA 128M x 64N, K=64 one-shot. grid (64, 32, 4).
// ===========================================================================
__global__ __launch_bounds__(256) void lora_s2(
    const int* __restrict__ ids, float* __restrict__ out)
{
    __shared__ __align__(128) uint8_t sXh[128 * 128];   // Bx [m][k]
    __shared__ __align__(128) uint8_t sXl[128 * 128];
    __shared__ __align__(128) uint8_t sAh[64 * 128];    // At [o][k]
    __shared__ __align__(128) uint8_t sAl[64 * 128];

    const int tid = threadIdx.x, lane = tid & 31, wid = tid >> 5;
    const int wm = wid & 3, wn = wid >> 2;
    const int o0 = blockIdx.x * 64, m0 = blockIdx.y * 128, b = blockIdx.z;
    const int a = ids[b];

    // ---- fill smem (operands already bf16 K-major in gmem) ----
    #pragma unroll
    for (int i = 0; i < 4; ++i) {
        int idx = tid + i * 256;             // 1024 uint4 slots
        int row = idx >> 3, rg = idx & 7;
        uint32_t so = SW128((uint32_t)row * 128 + rg * 16);
        size_t bx = (size_t)(b * SEQ + m0 + row) * 8 + rg;
        *(uint4*)(sXh + so) = ((const uint4*)g_bxh)[bx];
        *(uint4*)(sXl + so) = ((const uint4*)g_bxl)[bx];
    }
    #pragma unroll
    for (int i = 0; i < 2; ++i) {
        int idx = tid + i * 256;             // 512 uint4 slots
        int row = idx >> 3, rg = idx & 7;
        uint32_t so = SW128((uint32_t)row * 128 + rg * 16);
        size_t at = (size_t)(a * OUTF + o0 + row) * 8 + rg;
        *(uint4*)(sAh + so) = ((const uint4*)g_ath)[at];
        *(uint4*)(sAl + so) = ((const uint4*)g_atl)[at];
    }
    __syncthreads();

    const uint32_t xh_b = smem_u32(sXh), xl_b = smem_u32(sXl);
    const uint32_t nh_b = smem_u32(sAh), nl_b = smem_u32(sAl);
    const int lr = lane & 15;
    const uint32_t lcol = (uint32_t)(lane >> 4) * 16;

    uint32_t aterm[2], axor[2], bterm[2], bxor[2];
    #pragma unroll
    for (int t = 0; t < 2; ++t) {
        int ar = wm * 32 + t * 16 + lr;
        aterm[t] = (uint32_t)ar * 128; axor[t] = (uint32_t)(ar & 7) << 4;
        int br = wn * 32 + t * 16 + lr;
        bterm[t] = (uint32_t)br * 128; bxor[t] = (uint32_t)(br & 7) << 4;
    }

    float acc[2][4][4];
    #pragma unroll
    for (int i = 0; i < 2; ++i)
        #pragma unroll
        for (int j = 0; j < 4; ++j)
            #pragma unroll
            for (int k = 0; k < 4; ++k) acc[i][j][k] = 0.f;

    #pragma unroll
    for (int ks = 0; ks < 4; ++ks) {
        uint32_t cb = lcol + (uint32_t)ks * 32;
        uint32_t ah0[4], ah1[4], al0[4], al1[4];
        ldsm4(ah0, xh_b + aterm[0] + (cb ^ axor[0]));
        ldsm4(ah1, xh_b + aterm[1] + (cb ^ axor[1]));
        ldsm4(al0, xl_b + aterm[0] + (cb ^ axor[0]));
        ldsm4(al1, xl_b + aterm[1] + (cb ^ axor[1]));
        uint32_t bh0[4], bh1[4], bl0[4], bl1[4];
        ldsm4(bh0, nh_b + bterm[0] + (cb ^ bxor[0]));
        ldsm4(bh1, nh_b + bterm[1] + (cb ^ bxor[1]));
        ldsm4(bl0, nl_b + bterm[0] + (cb ^ bxor[0]));
        ldsm4(bl1, nl_b + bterm[1] + (cb ^ bxor[1]));

        mma3(acc[0][0], ah0, al0, bh0[0], bh0[2], bl0[0], bl0[2]);
        mma3(acc[0][1], ah0, al0, bh0[1], bh0[3], bl0[1], bl0[3]);
        mma3(acc[0][2], ah0, al0, bh1[0], bh1[2], bl1[0], bl1[2]);
        mma3(acc[0][3], ah0, al0, bh1[1], bh1[3], bl1[1], bl1[3]);
        mma3(acc[1][0], ah1, al1, bh0[0], bh0[2], bl0[0], bl0[2]);
        mma3(acc[1][1], ah1, al1, bh0[1], bh0[3], bl0[1], bl0[3]);
        mma3(acc[1][2], ah1, al1, bh1[0], bh1[2], bl1[0], bl1[2]);
        mma3(acc[1][3], ah1, al1, bh1[1], bh1[3], bl1[1], bl1[3]);
    }

    // ---- epilogue: scaled direct stores (float2 per c-pair) ----
    const float sc = 1.0f / (float)RANK;
    #pragma unroll
    for (int mt = 0; mt < 2; ++mt)
        #pragma unroll
        for (int nt = 0; nt < 4; ++nt) {
            int row = m0 + wm * 32 + mt * 16 + (lane >> 2);
            int col = o0 + wn * 32 + nt * 8 + 2 * (lane & 3);
            float2 v0 = { acc[mt][nt][0] * sc, acc[mt][nt][1] * sc };
            float2 v1 = { acc[mt][nt][2] * sc, acc[mt][nt][3] * sc };
            *(float2*)(out + (size_t)(b * SEQ + row)     * OUTF + col) = v0;
            *(float2*)(out + (size_t)(b * SEQ + row + 8) * OUTF + col) = v1;
        }
}

// ===========================================================================
extern "C" void kernel_launch(void* const* d_in, const int* in_sizes, int n_in,
                              void* d_out, int out_size)
{
    const float* x   = (const float*)d_in[0];
    const int*   ids = (const int*)  d_in[1];
    const float* A   = (const float*)d_in[2];
    const float* Bw  = (const float*)d_in[3];
    float* out = (float*)d_out;

    lora_prep_a<<<dim3(OUTF / 128, NADAPT), 256>>>(A);
    lora_s1<<<dim3(SEQ / 128, BATCH), 256>>>(x, ids, Bw);
    lora_s2<<<dim3(OUTF / 64, SEQ / 128, BATCH), 256>>>(ids, out);
}